// round 6
// baseline (speedup 1.0000x reference)
#include <cuda_runtime.h>
#include <cuda_fp16.h>
#include <cuda_bf16.h>

#define NN 100000
#define EE 1600000
#define FD 128
#define NG 128
#define OD 16

// Scratch (device globals — no allocs allowed)
__device__ float  g_deg[NN];                // dinv = rsqrt(indeg+1)
__device__ int    g_cnt_i[NN];              // in-degree counts
__device__ int    g_off[NN + 1];            // CSR row offsets
__device__ int    g_pos[NN];                // scatter cursors
__device__ int    g_csr_src[EE];            // src ids grouped by dst
__device__ __half g_bufA_h[(long)NN * FD];  // GEMM output, fp16 (gather source)
__device__ float  g_bufB[(long)NN * FD];    // layer-1 output, fp32 (GEMM2 input)
__device__ float  g_pool[NG * FD];
__device__ float  g_cnt[NG];

// ---------------- CSR build ----------------
__global__ void k_count_init(int n) {
    int i = blockIdx.x * blockDim.x + threadIdx.x;
    if (i < n) g_cnt_i[i] = 0;
}

__global__ void k_count(const int* __restrict__ ei, int e) {
    int stride = gridDim.x * blockDim.x;
    for (int i = blockIdx.x * blockDim.x + threadIdx.x; i < e; i += stride) {
        int d = ei[e + i];
        if ((unsigned)d < NN) atomicAdd(&g_cnt_i[d], 1);
    }
}

__global__ __launch_bounds__(1024) void k_scan(int n) {
    __shared__ int part[1024];
    int t = threadIdx.x;
    int chunk = (n + 1023) / 1024;
    int lo = t * chunk, hi = min(lo + chunk, n);
    int s = 0;
    for (int i = lo; i < hi; i++) s += g_cnt_i[i];
    part[t] = s;
    __syncthreads();
    for (int off = 1; off < 1024; off <<= 1) {
        int tmp = (t >= off) ? part[t - off] : 0;
        __syncthreads();
        part[t] += tmp;
        __syncthreads();
    }
    int run = part[t] - s;  // exclusive base
    for (int i = lo; i < hi; i++) {
        int c = g_cnt_i[i];
        g_off[i] = run;
        g_pos[i] = run;
        g_deg[i] = rsqrtf((float)(c + 1));
        run += c;
    }
    if (t == 1023) g_off[n] = part[1023];
}

__global__ void k_scatter(const int* __restrict__ ei, int e) {
    int stride = gridDim.x * blockDim.x;
    for (int i = blockIdx.x * blockDim.x + threadIdx.x; i < e; i += stride) {
        int s = ei[i];
        int d = ei[e + i];
        if ((unsigned)s >= NN || (unsigned)d >= NN) continue;
        int p = atomicAdd(&g_pos[d], 1);
        g_csr_src[p] = s;
    }
}

__global__ void k_pool_init() {
    int i = blockIdx.x * blockDim.x + threadIdx.x;
    if (i < NG * FD) g_pool[i] = 0.f;
    if (i < NG) g_cnt[i] = 0.f;
}

// ---------------- GEMM: g_bufA_h = (A @ W) as fp16 ----------------
__global__ __launch_bounds__(256) void k_gemm(
    const float* __restrict__ Ax, const float* __restrict__ W,
    int M, int src_sel)
{
    const float* __restrict__ A = src_sel ? (const float*)g_bufB : Ax;
    __shared__ float As[16][128];
    __shared__ float Ws[16][128];
    const int tid = threadIdx.x;
    const int row0 = blockIdx.x * 128;
    const int ty = tid >> 4, tx = tid & 15;
    const int m0 = ty * 8, n0 = tx * 8;
    const int lm = tid & 127;

    float acc[8][8];
#pragma unroll
    for (int i = 0; i < 8; i++)
#pragma unroll
        for (int j = 0; j < 8; j++) acc[i][j] = 0.f;

    for (int kt = 0; kt < 128; kt += 16) {
        int mA = row0 + lm;
#pragma unroll
        for (int i = 0; i < 2; i++) {
            int q = ((tid >> 7) << 1) + i;
            float4 v = make_float4(0.f, 0.f, 0.f, 0.f);
            if (mA < M) v = *(const float4*)(A + (long)mA * 128 + kt + q * 4);
            As[q * 4 + 0][lm] = v.x;
            As[q * 4 + 1][lm] = v.y;
            As[q * 4 + 2][lm] = v.z;
            As[q * 4 + 3][lm] = v.w;
        }
#pragma unroll
        for (int i = 0; i < 2; i++) {
            int idx = tid + i * 256;
            int k = idx >> 5;
            int n4 = (idx & 31) * 4;
            *(float4*)&Ws[k][n4] = *(const float4*)(W + (long)(kt + k) * 128 + n4);
        }
        __syncthreads();
#pragma unroll
        for (int k = 0; k < 16; k++) {
            float a[8], b[8];
            *(float4*)(a)     = *(float4*)&As[k][m0];
            *(float4*)(a + 4) = *(float4*)&As[k][m0 + 4];
            *(float4*)(b)     = *(float4*)&Ws[k][n0];
            *(float4*)(b + 4) = *(float4*)&Ws[k][n0 + 4];
#pragma unroll
            for (int i = 0; i < 8; i++)
#pragma unroll
                for (int j = 0; j < 8; j++)
                    acc[i][j] = fmaf(a[i], b[j], acc[i][j]);
        }
        __syncthreads();
    }
    // Epilogue: convert to fp16, 8 features -> one 16B store
#pragma unroll
    for (int i = 0; i < 8; i++) {
        int m = row0 + m0 + i;
        if (m < M) {
            __half2 h0 = __floats2half2_rn(acc[i][0], acc[i][1]);
            __half2 h1 = __floats2half2_rn(acc[i][2], acc[i][3]);
            __half2 h2 = __floats2half2_rn(acc[i][4], acc[i][5]);
            __half2 h3 = __floats2half2_rn(acc[i][6], acc[i][7]);
            uint4 pk;
            pk.x = *(unsigned*)&h0; pk.y = *(unsigned*)&h1;
            pk.z = *(unsigned*)&h2; pk.w = *(unsigned*)&h3;
            *(uint4*)((char*)g_bufA_h + (long)m * 256 + n0 * 2) = pk;
        }
    }
}

// lane's 4-feature fp16 slice of node s, as float4
__device__ __forceinline__ float4 ld_row_h(int s, int lane) {
    uint2 u = *((const uint2*)((const char*)g_bufA_h + (long)s * 256) + lane);
    float2 f0 = __half22float2(*(const __half2*)&u.x);
    float2 f1 = __half22float2(*(const __half2*)&u.y);
    return make_float4(f0.x, f0.y, f1.x, f1.y);
}

// per-node body: acc = Σ_{s ∈ N(d) ∪ {d}} dinv[s] * bufA[s]  (lane's slice)
__device__ __forceinline__ float4 node_gather(int d, int lane) {
    float dd = g_deg[d];
    float4 self = ld_row_h(d, lane);
    float4 acc = make_float4(self.x * dd, self.y * dd, self.z * dd, self.w * dd);
    int lo = g_off[d], hi = g_off[d + 1];
    int j = lo;
    for (; j + 3 < hi; j += 4) {
        int s0 = g_csr_src[j], s1 = g_csr_src[j + 1];
        int s2 = g_csr_src[j + 2], s3 = g_csr_src[j + 3];
        float d0 = g_deg[s0], d1 = g_deg[s1], d2 = g_deg[s2], d3 = g_deg[s3];
        float4 v0 = ld_row_h(s0, lane);
        float4 v1 = ld_row_h(s1, lane);
        float4 v2 = ld_row_h(s2, lane);
        float4 v3 = ld_row_h(s3, lane);
        acc.x = fmaf(v0.x, d0, fmaf(v1.x, d1, fmaf(v2.x, d2, fmaf(v3.x, d3, acc.x))));
        acc.y = fmaf(v0.y, d0, fmaf(v1.y, d1, fmaf(v2.y, d2, fmaf(v3.y, d3, acc.y))));
        acc.z = fmaf(v0.z, d0, fmaf(v1.z, d1, fmaf(v2.z, d2, fmaf(v3.z, d3, acc.z))));
        acc.w = fmaf(v0.w, d0, fmaf(v1.w, d1, fmaf(v2.w, d2, fmaf(v3.w, d3, acc.w))));
    }
    for (; j < hi; j++) {
        int s = g_csr_src[j];
        float ds = g_deg[s];
        float4 v = ld_row_h(s, lane);
        acc.x = fmaf(v.x, ds, acc.x);
        acc.y = fmaf(v.y, ds, acc.y);
        acc.z = fmaf(v.z, ds, acc.z);
        acc.w = fmaf(v.w, ds, acc.w);
    }
    return acc;
}

// ---------------- layer-1 aggregate: bufB = relu(dinv[d]*acc + b) ----------
__global__ __launch_bounds__(256) void k_aggregate(const float* __restrict__ bias, int n) {
    int w = (blockIdx.x * blockDim.x + threadIdx.x) >> 5;
    int lane = threadIdx.x & 31;
    int nw = (gridDim.x * blockDim.x) >> 5;
    float4 b = *(const float4*)(bias + lane * 4);
    for (int d = w; d < n; d += nw) {
        float4 acc = node_gather(d, lane);
        float sc = g_deg[d];
        float4 o;
        o.x = fmaxf(fmaf(sc, acc.x, b.x), 0.f);
        o.y = fmaxf(fmaf(sc, acc.y, b.y), 0.f);
        o.z = fmaxf(fmaf(sc, acc.z, b.z), 0.f);
        o.w = fmaxf(fmaf(sc, acc.w, b.w), 0.f);
        *(float4*)(g_bufB + (long)d * 128 + lane * 4) = o;
    }
}

// ---------------- layer-2 aggregate fused with mean-pool accumulation ------
__global__ __launch_bounds__(256) void k_agg_pool(
    const float* __restrict__ bias, const int* __restrict__ batch, int n)
{
    int w = (blockIdx.x * blockDim.x + threadIdx.x) >> 5;
    int lane = threadIdx.x & 31;
    int nw = (gridDim.x * blockDim.x) >> 5;
    int npb = (n + nw - 1) / nw;
    int n0 = w * npb;
    int n1 = min(n0 + npb, n);
    if (n0 >= n1) return;
    float4 b = *(const float4*)(bias + lane * 4);
    float4 pacc = make_float4(0.f, 0.f, 0.f, 0.f);
    float cnt = 0.f;
    int cg = batch[n0];
    for (int d = n0; d < n1; d++) {
        int g = batch[d];
        if (g != cg) {
            if ((unsigned)cg < NG) {
                float* p = g_pool + cg * FD + lane * 4;
                atomicAdd(p + 0, pacc.x); atomicAdd(p + 1, pacc.y);
                atomicAdd(p + 2, pacc.z); atomicAdd(p + 3, pacc.w);
                if (lane == 0) atomicAdd(&g_cnt[cg], cnt);
            }
            pacc = make_float4(0.f, 0.f, 0.f, 0.f); cnt = 0.f; cg = g;
        }
        float4 acc = node_gather(d, lane);
        float sc = g_deg[d];
        pacc.x += fmaxf(fmaf(sc, acc.x, b.x), 0.f);
        pacc.y += fmaxf(fmaf(sc, acc.y, b.y), 0.f);
        pacc.z += fmaxf(fmaf(sc, acc.z, b.z), 0.f);
        pacc.w += fmaxf(fmaf(sc, acc.w, b.w), 0.f);
        cnt += 1.f;
    }
    if ((unsigned)cg < NG) {
        float* p = g_pool + cg * FD + lane * 4;
        atomicAdd(p + 0, pacc.x); atomicAdd(p + 1, pacc.y);
        atomicAdd(p + 2, pacc.z); atomicAdd(p + 3, pacc.w);
        if (lane == 0) atomicAdd(&g_cnt[cg], cnt);
    }
}

// ---------------- final linear ----------------
__global__ void k_final(const float* __restrict__ wc, const float* __restrict__ bc,
                        float* __restrict__ out) {
    int g = blockIdx.x;
    int o = threadIdx.x;
    if (o >= OD) return;
    float inv = 1.f / fmaxf(g_cnt[g], 1.f);
    float s = 0.f;
#pragma unroll 8
    for (int f = 0; f < FD; f++)
        s = fmaf(g_pool[g * FD + f], wc[f * OD + o], s);
    out[g * OD + o] = s * inv + bc[o];
}

extern "C" void kernel_launch(void* const* d_in, const int* in_sizes, int n_in,
                              void* d_out, int out_size) {
    const float* x     = (const float*)d_in[0];
    const int*   ei    = (const int*)d_in[1];
    const int*   batch = (const int*)d_in[2];
    const float* w1    = (const float*)d_in[3];
    const float* b1    = (const float*)d_in[4];
    const float* w2    = (const float*)d_in[5];
    const float* b2    = (const float*)d_in[6];
    const float* wc    = (const float*)d_in[7];
    const float* bc    = (const float*)d_in[8];
    float* out = (float*)d_out;

    int n = in_sizes[0] / FD;      // 100000
    int e = in_sizes[1] / 2;       // 1600000
    int gemm_blocks = (n + 127) / 128;

    static cudaStream_t s_side = nullptr;
    static cudaEvent_t ev_fork = nullptr, ev_join = nullptr;
    if (!s_side) {
        cudaStreamCreateWithFlags(&s_side, cudaStreamNonBlocking);
        cudaEventCreateWithFlags(&ev_fork, cudaEventDisableTiming);
        cudaEventCreateWithFlags(&ev_join, cudaEventDisableTiming);
    }

    // fork: CSR build + pool init on side stream, GEMM1 on main stream
    cudaEventRecord(ev_fork, 0);
    cudaStreamWaitEvent(s_side, ev_fork, 0);
    k_count_init<<<(n + 255) / 256, 256, 0, s_side>>>(n);
    k_count<<<1024, 256, 0, s_side>>>(ei, e);
    k_scan<<<1, 1024, 0, s_side>>>(n);
    k_scatter<<<1024, 256, 0, s_side>>>(ei, e);
    k_pool_init<<<(NG * FD + 255) / 256, 256, 0, s_side>>>();
    cudaEventRecord(ev_join, s_side);

    k_gemm<<<gemm_blocks, 256>>>(x, w1, n, 0);
    cudaStreamWaitEvent(0, ev_join, 0);

    // layer 1
    k_aggregate<<<4096, 256>>>(b1, n);
    // layer 2 (aggregate fused with pooling)
    k_gemm<<<gemm_blocks, 256>>>(x, w2, n, 1);
    k_agg_pool<<<2048, 256>>>(b2, batch, n);

    k_final<<<NG, 32>>>(wc, bc, out);
}

// round 7
// speedup vs baseline: 1.0812x; 1.0812x over previous
#include <cuda_runtime.h>
#include <cuda_fp16.h>
#include <cuda_bf16.h>

#define NN 100000
#define EE 1600000
#define FD 128
#define NG 128
#define OD 16

// Scratch (device globals — no allocs allowed)
__device__ float  g_deg[NN];                // dinv = rsqrt(indeg+1)
__device__ int    g_cnt_i[NN];              // in-degree counts
__device__ int    g_off[NN + 1];            // CSR row offsets
__device__ int    g_pos[NN];                // scatter cursors
__device__ int    g_csr_src[EE];            // src ids grouped by dst
__device__ __half g_bufA_h[(long)NN * FD];  // dinv-prescaled GEMM output, fp16
__device__ float  g_bufB[(long)NN * FD];    // layer-1 output, fp32 (GEMM2 input)
__device__ float  g_pool[NG * FD];
__device__ float  g_cnt[NG];

// ---------------- CSR build ----------------
__global__ void k_count_init(int n) {
    int i = blockIdx.x * blockDim.x + threadIdx.x;
    if (i < n) g_cnt_i[i] = 0;
}

__global__ void k_count(const int* __restrict__ ei, int e) {
    int stride = gridDim.x * blockDim.x;
    for (int i = blockIdx.x * blockDim.x + threadIdx.x; i < e; i += stride) {
        int d = ei[e + i];
        if ((unsigned)d < NN) atomicAdd(&g_cnt_i[d], 1);
    }
}

__global__ __launch_bounds__(1024) void k_scan(int n) {
    __shared__ int part[1024];
    int t = threadIdx.x;
    int chunk = (n + 1023) / 1024;
    int lo = t * chunk, hi = min(lo + chunk, n);
    int s = 0;
    for (int i = lo; i < hi; i++) s += g_cnt_i[i];
    part[t] = s;
    __syncthreads();
    for (int off = 1; off < 1024; off <<= 1) {
        int tmp = (t >= off) ? part[t - off] : 0;
        __syncthreads();
        part[t] += tmp;
        __syncthreads();
    }
    int run = part[t] - s;  // exclusive base
    for (int i = lo; i < hi; i++) {
        int c = g_cnt_i[i];
        g_off[i] = run;
        g_pos[i] = run;
        g_deg[i] = rsqrtf((float)(c + 1));
        run += c;
    }
    if (t == 1023) g_off[n] = part[1023];
}

__global__ void k_scatter(const int* __restrict__ ei, int e) {
    int stride = gridDim.x * blockDim.x;
    for (int i = blockIdx.x * blockDim.x + threadIdx.x; i < e; i += stride) {
        int s = ei[i];
        int d = ei[e + i];
        if ((unsigned)s >= NN || (unsigned)d >= NN) continue;
        int p = atomicAdd(&g_pos[d], 1);
        g_csr_src[p] = s;
    }
}

__global__ void k_pool_init() {
    int i = blockIdx.x * blockDim.x + threadIdx.x;
    if (i < NG * FD) g_pool[i] = 0.f;
    if (i < NG) g_cnt[i] = 0.f;
}

// ---------------- GEMM: g_bufA_h = dinv[m] * (A @ W), fp16 ----------------
__global__ __launch_bounds__(256) void k_gemm(
    const float* __restrict__ Ax, const float* __restrict__ W,
    int M, int src_sel)
{
    const float* __restrict__ A = src_sel ? (const float*)g_bufB : Ax;
    __shared__ float As[16][128];
    __shared__ float Ws[16][128];
    const int tid = threadIdx.x;
    const int row0 = blockIdx.x * 128;
    const int ty = tid >> 4, tx = tid & 15;
    const int m0 = ty * 8, n0 = tx * 8;
    const int lm = tid & 127;

    float acc[8][8];
#pragma unroll
    for (int i = 0; i < 8; i++)
#pragma unroll
        for (int j = 0; j < 8; j++) acc[i][j] = 0.f;

    for (int kt = 0; kt < 128; kt += 16) {
        int mA = row0 + lm;
#pragma unroll
        for (int i = 0; i < 2; i++) {
            int q = ((tid >> 7) << 1) + i;
            float4 v = make_float4(0.f, 0.f, 0.f, 0.f);
            if (mA < M) v = *(const float4*)(A + (long)mA * 128 + kt + q * 4);
            As[q * 4 + 0][lm] = v.x;
            As[q * 4 + 1][lm] = v.y;
            As[q * 4 + 2][lm] = v.z;
            As[q * 4 + 3][lm] = v.w;
        }
#pragma unroll
        for (int i = 0; i < 2; i++) {
            int idx = tid + i * 256;
            int k = idx >> 5;
            int n4 = (idx & 31) * 4;
            *(float4*)&Ws[k][n4] = *(const float4*)(W + (long)(kt + k) * 128 + n4);
        }
        __syncthreads();
#pragma unroll
        for (int k = 0; k < 16; k++) {
            float a[8], b[8];
            *(float4*)(a)     = *(float4*)&As[k][m0];
            *(float4*)(a + 4) = *(float4*)&As[k][m0 + 4];
            *(float4*)(b)     = *(float4*)&Ws[k][n0];
            *(float4*)(b + 4) = *(float4*)&Ws[k][n0 + 4];
#pragma unroll
            for (int i = 0; i < 8; i++)
#pragma unroll
                for (int j = 0; j < 8; j++)
                    acc[i][j] = fmaf(a[i], b[j], acc[i][j]);
        }
        __syncthreads();
    }
    // Epilogue: prescale by dinv[m], convert to fp16, one 16B store per row-slice
#pragma unroll
    for (int i = 0; i < 8; i++) {
        int m = row0 + m0 + i;
        if (m < M) {
            float s = g_deg[m];
            __half2 h0 = __floats2half2_rn(acc[i][0] * s, acc[i][1] * s);
            __half2 h1 = __floats2half2_rn(acc[i][2] * s, acc[i][3] * s);
            __half2 h2 = __floats2half2_rn(acc[i][4] * s, acc[i][5] * s);
            __half2 h3 = __floats2half2_rn(acc[i][6] * s, acc[i][7] * s);
            uint4 pk;
            pk.x = *(unsigned*)&h0; pk.y = *(unsigned*)&h1;
            pk.z = *(unsigned*)&h2; pk.w = *(unsigned*)&h3;
            *(uint4*)((char*)g_bufA_h + (long)m * 256 + n0 * 2) = pk;
        }
    }
}

// lane's 4-feature fp16 slice of node s, as float4
__device__ __forceinline__ float4 ld_row_h(int s, int lane) {
    uint2 u = __ldg((const uint2*)((const char*)g_bufA_h + (long)s * 256) + lane);
    float2 f0 = __half22float2(*(const __half2*)&u.x);
    float2 f1 = __half22float2(*(const __half2*)&u.y);
    return make_float4(f0.x, f0.y, f1.x, f1.y);
}

// acc = Σ_{s ∈ N(d) ∪ {d}} bufA[s]   (rows already dinv-prescaled)
__device__ __forceinline__ float4 node_gather(int d, int lane) {
    float4 acc = ld_row_h(d, lane);  // self-loop
    int lo = g_off[d], hi = g_off[d + 1];
    int j = lo;
    int lo4 = min((lo + 3) & ~3, hi);
    for (; j < lo4; j++) {
        float4 v = ld_row_h(g_csr_src[j], lane);
        acc.x += v.x; acc.y += v.y; acc.z += v.z; acc.w += v.w;
    }
    for (; j + 7 < hi; j += 8) {
        int4 sa = *(const int4*)(g_csr_src + j);
        int4 sb = *(const int4*)(g_csr_src + j + 4);
        float4 v0 = ld_row_h(sa.x, lane);
        float4 v1 = ld_row_h(sa.y, lane);
        float4 v2 = ld_row_h(sa.z, lane);
        float4 v3 = ld_row_h(sa.w, lane);
        float4 v4 = ld_row_h(sb.x, lane);
        float4 v5 = ld_row_h(sb.y, lane);
        float4 v6 = ld_row_h(sb.z, lane);
        float4 v7 = ld_row_h(sb.w, lane);
        acc.x += ((v0.x + v1.x) + (v2.x + v3.x)) + ((v4.x + v5.x) + (v6.x + v7.x));
        acc.y += ((v0.y + v1.y) + (v2.y + v3.y)) + ((v4.y + v5.y) + (v6.y + v7.y));
        acc.z += ((v0.z + v1.z) + (v2.z + v3.z)) + ((v4.z + v5.z) + (v6.z + v7.z));
        acc.w += ((v0.w + v1.w) + (v2.w + v3.w)) + ((v4.w + v5.w) + (v6.w + v7.w));
    }
    for (; j + 3 < hi; j += 4) {
        int4 sa = *(const int4*)(g_csr_src + j);
        float4 v0 = ld_row_h(sa.x, lane);
        float4 v1 = ld_row_h(sa.y, lane);
        float4 v2 = ld_row_h(sa.z, lane);
        float4 v3 = ld_row_h(sa.w, lane);
        acc.x += (v0.x + v1.x) + (v2.x + v3.x);
        acc.y += (v0.y + v1.y) + (v2.y + v3.y);
        acc.z += (v0.z + v1.z) + (v2.z + v3.z);
        acc.w += (v0.w + v1.w) + (v2.w + v3.w);
    }
    for (; j < hi; j++) {
        float4 v = ld_row_h(g_csr_src[j], lane);
        acc.x += v.x; acc.y += v.y; acc.z += v.z; acc.w += v.w;
    }
    return acc;
}

// ---------------- layer-1 aggregate: bufB = relu(dinv[d]*acc + b) ----------
__global__ __launch_bounds__(256) void k_aggregate(const float* __restrict__ bias, int n) {
    int w = (blockIdx.x * blockDim.x + threadIdx.x) >> 5;
    int lane = threadIdx.x & 31;
    int nw = (gridDim.x * blockDim.x) >> 5;
    float4 b = *(const float4*)(bias + lane * 4);
    for (int d = w; d < n; d += nw) {
        float4 acc = node_gather(d, lane);
        float sc = g_deg[d];
        float4 o;
        o.x = fmaxf(fmaf(sc, acc.x, b.x), 0.f);
        o.y = fmaxf(fmaf(sc, acc.y, b.y), 0.f);
        o.z = fmaxf(fmaf(sc, acc.z, b.z), 0.f);
        o.w = fmaxf(fmaf(sc, acc.w, b.w), 0.f);
        __stcs((float4*)(g_bufB + (long)d * 128 + lane * 4), o);
    }
}

// ---------------- layer-2 aggregate fused with mean-pool accumulation ------
__global__ __launch_bounds__(256) void k_agg_pool(
    const float* __restrict__ bias, const int* __restrict__ batch, int n)
{
    int w = (blockIdx.x * blockDim.x + threadIdx.x) >> 5;
    int lane = threadIdx.x & 31;
    int nw = (gridDim.x * blockDim.x) >> 5;
    int npb = (n + nw - 1) / nw;
    int n0 = w * npb;
    int n1 = min(n0 + npb, n);
    if (n0 >= n1) return;
    float4 b = *(const float4*)(bias + lane * 4);
    float4 pacc = make_float4(0.f, 0.f, 0.f, 0.f);
    float cnt = 0.f;
    int cg = batch[n0];
    for (int d = n0; d < n1; d++) {
        int g = batch[d];
        if (g != cg) {
            if ((unsigned)cg < NG) {
                float* p = g_pool + cg * FD + lane * 4;
                atomicAdd(p + 0, pacc.x); atomicAdd(p + 1, pacc.y);
                atomicAdd(p + 2, pacc.z); atomicAdd(p + 3, pacc.w);
                if (lane == 0) atomicAdd(&g_cnt[cg], cnt);
            }
            pacc = make_float4(0.f, 0.f, 0.f, 0.f); cnt = 0.f; cg = g;
        }
        float4 acc = node_gather(d, lane);
        float sc = g_deg[d];
        pacc.x += fmaxf(fmaf(sc, acc.x, b.x), 0.f);
        pacc.y += fmaxf(fmaf(sc, acc.y, b.y), 0.f);
        pacc.z += fmaxf(fmaf(sc, acc.z, b.z), 0.f);
        pacc.w += fmaxf(fmaf(sc, acc.w, b.w), 0.f);
        cnt += 1.f;
    }
    if ((unsigned)cg < NG) {
        float* p = g_pool + cg * FD + lane * 4;
        atomicAdd(p + 0, pacc.x); atomicAdd(p + 1, pacc.y);
        atomicAdd(p + 2, pacc.z); atomicAdd(p + 3, pacc.w);
        if (lane == 0) atomicAdd(&g_cnt[cg], cnt);
    }
}

// ---------------- final linear ----------------
__global__ void k_final(const float* __restrict__ wc, const float* __restrict__ bc,
                        float* __restrict__ out) {
    int g = blockIdx.x;
    int o = threadIdx.x;
    if (o >= OD) return;
    float inv = 1.f / fmaxf(g_cnt[g], 1.f);
    float s = 0.f;
#pragma unroll 8
    for (int f = 0; f < FD; f++)
        s = fmaf(g_pool[g * FD + f], wc[f * OD + o], s);
    out[g * OD + o] = s * inv + bc[o];
}

extern "C" void kernel_launch(void* const* d_in, const int* in_sizes, int n_in,
                              void* d_out, int out_size) {
    const float* x     = (const float*)d_in[0];
    const int*   ei    = (const int*)d_in[1];
    const int*   batch = (const int*)d_in[2];
    const float* w1    = (const float*)d_in[3];
    const float* b1    = (const float*)d_in[4];
    const float* w2    = (const float*)d_in[5];
    const float* b2    = (const float*)d_in[6];
    const float* wc    = (const float*)d_in[7];
    const float* bc    = (const float*)d_in[8];
    float* out = (float*)d_out;

    int n = in_sizes[0] / FD;      // 100000
    int e = in_sizes[1] / 2;       // 1600000
    int gemm_blocks = (n + 127) / 128;

    static cudaStream_t s_side = nullptr;
    static cudaEvent_t ev_fork = nullptr, ev_join = nullptr;
    if (!s_side) {
        cudaStreamCreateWithFlags(&s_side, cudaStreamNonBlocking);
        cudaEventCreateWithFlags(&ev_fork, cudaEventDisableTiming);
        cudaEventCreateWithFlags(&ev_join, cudaEventDisableTiming);
    }

    // count + scan on main stream (gemm1 needs dinv from scan)
    k_count_init<<<(n + 255) / 256, 256>>>(n);
    k_count<<<1024, 256>>>(ei, e);
    k_scan<<<1, 1024>>>(n);

    // fork: scatter + pool_init on side stream, GEMM1 (needs only deg) on main
    cudaEventRecord(ev_fork, 0);
    cudaStreamWaitEvent(s_side, ev_fork, 0);
    k_scatter<<<1024, 256, 0, s_side>>>(ei, e);
    k_pool_init<<<(NG * FD + 255) / 256, 256, 0, s_side>>>();
    cudaEventRecord(ev_join, s_side);

    k_gemm<<<gemm_blocks, 256>>>(x, w1, n, 0);
    cudaStreamWaitEvent(0, ev_join, 0);

    // layer 1
    k_aggregate<<<4096, 256>>>(b1, n);
    // layer 2 (aggregate fused with pooling)
    k_gemm<<<gemm_blocks, 256>>>(x, w2, n, 1);
    k_agg_pool<<<2048, 256>>>(b2, batch, n);

    k_final<<<NG, 32>>>(wc, bc, out);
}

// round 8
// speedup vs baseline: 1.4286x; 1.3213x over previous
#include <cuda_runtime.h>
#include <cuda_fp16.h>
#include <cuda_bf16.h>
#include <cstdint>

#define NN 100000
#define EE 1600000
#define FD 128
#define NG 128
#define OD 16

#define SMS 136                         // smem halves per row (272B = 17*16B)
#define SMEM_GEMM (2 * 128 * SMS * 2)   // 69632 B

// Scratch (device globals — no allocs allowed)
__device__ float  g_deg[NN];                // dinv = rsqrt(indeg+1)
__device__ int    g_cnt_i[NN];              // in-degree counts
__device__ int    g_off[NN + 1];            // CSR row offsets
__device__ int    g_pos[NN];                // scatter cursors
__device__ int    g_csr_src[EE];            // src ids grouped by dst
__device__ __half g_bufA_h[(long)NN * FD];  // dinv-prescaled GEMM output, fp16
__device__ float  g_bufB[(long)NN * FD];    // layer-1 output, fp32 (GEMM2 input)
__device__ float  g_pool[NG * FD];
__device__ float  g_cnt[NG];

// ---------------- CSR build ----------------
__global__ void k_count_init(int n) {
    int i = blockIdx.x * blockDim.x + threadIdx.x;
    if (i < n) g_cnt_i[i] = 0;
}

__global__ void k_count(const int* __restrict__ ei, int e) {
    int stride = gridDim.x * blockDim.x;
    int gid = blockIdx.x * blockDim.x + threadIdx.x;
    const int4* dst4 = (const int4*)(ei + e);
    int e4 = e >> 2;
    for (int i = gid; i < e4; i += stride) {
        int4 d = dst4[i];
        if ((unsigned)d.x < NN) atomicAdd(&g_cnt_i[d.x], 1);
        if ((unsigned)d.y < NN) atomicAdd(&g_cnt_i[d.y], 1);
        if ((unsigned)d.z < NN) atomicAdd(&g_cnt_i[d.z], 1);
        if ((unsigned)d.w < NN) atomicAdd(&g_cnt_i[d.w], 1);
    }
    for (int i = (e4 << 2) + gid; i < e; i += stride) {
        int d = ei[e + i];
        if ((unsigned)d < NN) atomicAdd(&g_cnt_i[d], 1);
    }
}

__global__ __launch_bounds__(1024) void k_scan(int n) {
    __shared__ int part[1024];
    int t = threadIdx.x;
    int chunk = (n + 1023) / 1024;
    int lo = t * chunk, hi = min(lo + chunk, n);
    int s = 0;
    for (int i = lo; i < hi; i++) s += g_cnt_i[i];
    part[t] = s;
    __syncthreads();
    for (int off = 1; off < 1024; off <<= 1) {
        int tmp = (t >= off) ? part[t - off] : 0;
        __syncthreads();
        part[t] += tmp;
        __syncthreads();
    }
    int run = part[t] - s;  // exclusive base
    for (int i = lo; i < hi; i++) {
        int c = g_cnt_i[i];
        g_off[i] = run;
        g_pos[i] = run;
        g_deg[i] = rsqrtf((float)(c + 1));
        run += c;
    }
    if (t == 1023) g_off[n] = part[1023];
}

__global__ void k_scatter(const int* __restrict__ ei, int e) {
    int stride = gridDim.x * blockDim.x;
    int gid = blockIdx.x * blockDim.x + threadIdx.x;
    const int4* src4 = (const int4*)ei;
    const int4* dst4 = (const int4*)(ei + e);
    int e4 = e >> 2;
    for (int i = gid; i < e4; i += stride) {
        int4 s = src4[i];
        int4 d = dst4[i];
        if ((unsigned)s.x < NN && (unsigned)d.x < NN) g_csr_src[atomicAdd(&g_pos[d.x], 1)] = s.x;
        if ((unsigned)s.y < NN && (unsigned)d.y < NN) g_csr_src[atomicAdd(&g_pos[d.y], 1)] = s.y;
        if ((unsigned)s.z < NN && (unsigned)d.z < NN) g_csr_src[atomicAdd(&g_pos[d.z], 1)] = s.z;
        if ((unsigned)s.w < NN && (unsigned)d.w < NN) g_csr_src[atomicAdd(&g_pos[d.w], 1)] = s.w;
    }
    for (int i = (e4 << 2) + gid; i < e; i += stride) {
        int s = ei[i];
        int d = ei[e + i];
        if ((unsigned)s < NN && (unsigned)d < NN)
            g_csr_src[atomicAdd(&g_pos[d], 1)] = s;
    }
}

__global__ void k_pool_init() {
    int i = blockIdx.x * blockDim.x + threadIdx.x;
    if (i < NG * FD) g_pool[i] = 0.f;
    if (i < NG) g_cnt[i] = 0.f;
}

// ---------------- tensor-core GEMM: g_bufA_h = dinv[m] * (A @ W), fp16 -----
__device__ __forceinline__ void mma16816(float* c, const uint32_t* a,
                                         uint32_t b0, uint32_t b1) {
    asm volatile(
        "mma.sync.aligned.m16n8k16.row.col.f32.f16.f16.f32 "
        "{%0,%1,%2,%3}, {%4,%5,%6,%7}, {%8,%9}, {%0,%1,%2,%3};"
        : "+f"(c[0]), "+f"(c[1]), "+f"(c[2]), "+f"(c[3])
        : "r"(a[0]), "r"(a[1]), "r"(a[2]), "r"(a[3]), "r"(b0), "r"(b1));
}

__global__ __launch_bounds__(256) void k_gemm_tc(
    const float* __restrict__ Ax, const float* __restrict__ W,
    int M, int src_sel)
{
    extern __shared__ __align__(16) char smem_raw[];
    __half* As = (__half*)smem_raw;            // [128][SMS]
    __half* Ws = As + 128 * SMS;               // [128][SMS]
    const float* __restrict__ A = src_sel ? (const float*)g_bufB : Ax;
    const int tid = threadIdx.x;
    const int row0 = blockIdx.x * 128;

    // Load A block (fp32 -> fp16) and W block into smem
#pragma unroll
    for (int i = 0; i < 16; i++) {
        int idx = tid + i * 256;          // 0..4095
        int r = idx >> 5;
        int c4 = (idx & 31) << 2;
        int gr = row0 + r;
        float4 v = make_float4(0.f, 0.f, 0.f, 0.f);
        if (gr < M) v = *(const float4*)(A + (long)gr * 128 + c4);
        *(__half2*)(As + r * SMS + c4)     = __floats2half2_rn(v.x, v.y);
        *(__half2*)(As + r * SMS + c4 + 2) = __floats2half2_rn(v.z, v.w);
    }
#pragma unroll
    for (int i = 0; i < 16; i++) {
        int idx = tid + i * 256;
        int r = idx >> 5;
        int c4 = (idx & 31) << 2;
        float4 v = *(const float4*)(W + (long)r * 128 + c4);
        *(__half2*)(Ws + r * SMS + c4)     = __floats2half2_rn(v.x, v.y);
        *(__half2*)(Ws + r * SMS + c4 + 2) = __floats2half2_rn(v.z, v.w);
    }
    __syncthreads();

    const int warp = tid >> 5, lane = tid & 31;
    const int m_base = (warp >> 1) * 32;       // warp rows
    const int n_base = (warp & 1) * 64;        // warp cols

    float acc[2][8][4];
#pragma unroll
    for (int mt = 0; mt < 2; mt++)
#pragma unroll
        for (int nt = 0; nt < 8; nt++)
#pragma unroll
            for (int q = 0; q < 4; q++) acc[mt][nt][q] = 0.f;

    const int lrow = lane & 15;
    const int lcol = (lane >> 4) << 3;

#pragma unroll
    for (int ks = 0; ks < 8; ks++) {
        int k0 = ks * 16;
        uint32_t a[2][4];
#pragma unroll
        for (int mt = 0; mt < 2; mt++) {
            uint32_t addr = (uint32_t)__cvta_generic_to_shared(
                As + (m_base + mt * 16 + lrow) * SMS + k0 + lcol);
            asm volatile("ldmatrix.sync.aligned.m8n8.x4.shared.b16 {%0,%1,%2,%3}, [%4];"
                         : "=r"(a[mt][0]), "=r"(a[mt][1]), "=r"(a[mt][2]), "=r"(a[mt][3])
                         : "r"(addr));
        }
#pragma unroll
        for (int nt = 0; nt < 4; nt++) {
            uint32_t b[4];
            uint32_t addr = (uint32_t)__cvta_generic_to_shared(
                Ws + (k0 + lrow) * SMS + n_base + nt * 16 + lcol);
            asm volatile("ldmatrix.sync.aligned.m8n8.x4.trans.shared.b16 {%0,%1,%2,%3}, [%4];"
                         : "=r"(b[0]), "=r"(b[1]), "=r"(b[2]), "=r"(b[3])
                         : "r"(addr));
#pragma unroll
            for (int mt = 0; mt < 2; mt++) {
                mma16816(acc[mt][nt * 2],     a[mt], b[0], b[1]);
                mma16816(acc[mt][nt * 2 + 1], a[mt], b[2], b[3]);
            }
        }
    }

    // Epilogue: prescale by dinv, convert to fp16, store half2 pairs
    const int qr = lane >> 2;
    const int qc = (lane & 3) * 2;
#pragma unroll
    for (int mt = 0; mt < 2; mt++) {
        int r0 = row0 + m_base + mt * 16 + qr;
        int r1 = r0 + 8;
        float s0 = (r0 < M) ? g_deg[r0] : 0.f;
        float s1 = (r1 < M) ? g_deg[r1] : 0.f;
#pragma unroll
        for (int nt = 0; nt < 8; nt++) {
            int col = n_base + nt * 8 + qc;
            if (r0 < M)
                *(__half2*)((char*)g_bufA_h + (long)r0 * 256 + col * 2) =
                    __floats2half2_rn(acc[mt][nt][0] * s0, acc[mt][nt][1] * s0);
            if (r1 < M)
                *(__half2*)((char*)g_bufA_h + (long)r1 * 256 + col * 2) =
                    __floats2half2_rn(acc[mt][nt][2] * s1, acc[mt][nt][3] * s1);
        }
    }
}

// lane's 4-feature fp16 slice of node s, as float4
__device__ __forceinline__ float4 ld_row_h(int s, int lane) {
    uint2 u = __ldg((const uint2*)((const char*)g_bufA_h + (long)s * 256) + lane);
    float2 f0 = __half22float2(*(const __half2*)&u.x);
    float2 f1 = __half22float2(*(const __half2*)&u.y);
    return make_float4(f0.x, f0.y, f1.x, f1.y);
}

// acc = Σ_{s ∈ N(d) ∪ {d}} bufA[s]   (rows already dinv-prescaled)
__device__ __forceinline__ float4 node_gather(int d, int lane) {
    float4 acc = ld_row_h(d, lane);  // self-loop
    int lo = g_off[d], hi = g_off[d + 1];
    int j = lo;
    int lo4 = min((lo + 3) & ~3, hi);
    for (; j < lo4; j++) {
        float4 v = ld_row_h(g_csr_src[j], lane);
        acc.x += v.x; acc.y += v.y; acc.z += v.z; acc.w += v.w;
    }
    for (; j + 7 < hi; j += 8) {
        int4 sa = *(const int4*)(g_csr_src + j);
        int4 sb = *(const int4*)(g_csr_src + j + 4);
        float4 v0 = ld_row_h(sa.x, lane);
        float4 v1 = ld_row_h(sa.y, lane);
        float4 v2 = ld_row_h(sa.z, lane);
        float4 v3 = ld_row_h(sa.w, lane);
        float4 v4 = ld_row_h(sb.x, lane);
        float4 v5 = ld_row_h(sb.y, lane);
        float4 v6 = ld_row_h(sb.z, lane);
        float4 v7 = ld_row_h(sb.w, lane);
        acc.x += ((v0.x + v1.x) + (v2.x + v3.x)) + ((v4.x + v5.x) + (v6.x + v7.x));
        acc.y += ((v0.y + v1.y) + (v2.y + v3.y)) + ((v4.y + v5.y) + (v6.y + v7.y));
        acc.z += ((v0.z + v1.z) + (v2.z + v3.z)) + ((v4.z + v5.z) + (v6.z + v7.z));
        acc.w += ((v0.w + v1.w) + (v2.w + v3.w)) + ((v4.w + v5.w) + (v6.w + v7.w));
    }
    for (; j + 3 < hi; j += 4) {
        int4 sa = *(const int4*)(g_csr_src + j);
        float4 v0 = ld_row_h(sa.x, lane);
        float4 v1 = ld_row_h(sa.y, lane);
        float4 v2 = ld_row_h(sa.z, lane);
        float4 v3 = ld_row_h(sa.w, lane);
        acc.x += (v0.x + v1.x) + (v2.x + v3.x);
        acc.y += (v0.y + v1.y) + (v2.y + v3.y);
        acc.z += (v0.z + v1.z) + (v2.z + v3.z);
        acc.w += (v0.w + v1.w) + (v2.w + v3.w);
    }
    for (; j < hi; j++) {
        float4 v = ld_row_h(g_csr_src[j], lane);
        acc.x += v.x; acc.y += v.y; acc.z += v.z; acc.w += v.w;
    }
    return acc;
}

// ---------------- layer-1 aggregate: bufB = relu(dinv[d]*acc + b) ----------
__global__ __launch_bounds__(256) void k_aggregate(const float* __restrict__ bias, int n) {
    int w = (blockIdx.x * blockDim.x + threadIdx.x) >> 5;
    int lane = threadIdx.x & 31;
    int nw = (gridDim.x * blockDim.x) >> 5;
    float4 b = *(const float4*)(bias + lane * 4);
    for (int d = w; d < n; d += nw) {
        float4 acc = node_gather(d, lane);
        float sc = g_deg[d];
        float4 o;
        o.x = fmaxf(fmaf(sc, acc.x, b.x), 0.f);
        o.y = fmaxf(fmaf(sc, acc.y, b.y), 0.f);
        o.z = fmaxf(fmaf(sc, acc.z, b.z), 0.f);
        o.w = fmaxf(fmaf(sc, acc.w, b.w), 0.f);
        __stcs((float4*)(g_bufB + (long)d * 128 + lane * 4), o);
    }
}

// ---------------- layer-2 aggregate fused with mean-pool accumulation ------
__global__ __launch_bounds__(256) void k_agg_pool(
    const float* __restrict__ bias, const int* __restrict__ batch, int n)
{
    int w = (blockIdx.x * blockDim.x + threadIdx.x) >> 5;
    int lane = threadIdx.x & 31;
    int nw = (gridDim.x * blockDim.x) >> 5;
    int npb = (n + nw - 1) / nw;
    int n0 = w * npb;
    int n1 = min(n0 + npb, n);
    if (n0 >= n1) return;
    float4 b = *(const float4*)(bias + lane * 4);
    float4 pacc = make_float4(0.f, 0.f, 0.f, 0.f);
    float cnt = 0.f;
    int cg = batch[n0];
    for (int d = n0; d < n1; d++) {
        int g = batch[d];
        if (g != cg) {
            if ((unsigned)cg < NG) {
                float* p = g_pool + cg * FD + lane * 4;
                atomicAdd(p + 0, pacc.x); atomicAdd(p + 1, pacc.y);
                atomicAdd(p + 2, pacc.z); atomicAdd(p + 3, pacc.w);
                if (lane == 0) atomicAdd(&g_cnt[cg], cnt);
            }
            pacc = make_float4(0.f, 0.f, 0.f, 0.f); cnt = 0.f; cg = g;
        }
        float4 acc = node_gather(d, lane);
        float sc = g_deg[d];
        pacc.x += fmaxf(fmaf(sc, acc.x, b.x), 0.f);
        pacc.y += fmaxf(fmaf(sc, acc.y, b.y), 0.f);
        pacc.z += fmaxf(fmaf(sc, acc.z, b.z), 0.f);
        pacc.w += fmaxf(fmaf(sc, acc.w, b.w), 0.f);
        cnt += 1.f;
    }
    if ((unsigned)cg < NG) {
        float* p = g_pool + cg * FD + lane * 4;
        atomicAdd(p + 0, pacc.x); atomicAdd(p + 1, pacc.y);
        atomicAdd(p + 2, pacc.z); atomicAdd(p + 3, pacc.w);
        if (lane == 0) atomicAdd(&g_cnt[cg], cnt);
    }
}

// ---------------- final linear ----------------
__global__ void k_final(const float* __restrict__ wc, const float* __restrict__ bc,
                        float* __restrict__ out) {
    int g = blockIdx.x;
    int o = threadIdx.x;
    if (o >= OD) return;
    float inv = 1.f / fmaxf(g_cnt[g], 1.f);
    float s = 0.f;
#pragma unroll 8
    for (int f = 0; f < FD; f++)
        s = fmaf(g_pool[g * FD + f], wc[f * OD + o], s);
    out[g * OD + o] = s * inv + bc[o];
}

extern "C" void kernel_launch(void* const* d_in, const int* in_sizes, int n_in,
                              void* d_out, int out_size) {
    const float* x     = (const float*)d_in[0];
    const int*   ei    = (const int*)d_in[1];
    const int*   batch = (const int*)d_in[2];
    const float* w1    = (const float*)d_in[3];
    const float* b1    = (const float*)d_in[4];
    const float* w2    = (const float*)d_in[5];
    const float* b2    = (const float*)d_in[6];
    const float* wc    = (const float*)d_in[7];
    const float* bc    = (const float*)d_in[8];
    float* out = (float*)d_out;

    int n = in_sizes[0] / FD;      // 100000
    int e = in_sizes[1] / 2;       // 1600000
    int gemm_blocks = (n + 127) / 128;

    static cudaStream_t s_side = nullptr;
    static cudaEvent_t ev_fork = nullptr, ev_join = nullptr;
    static bool attr_set = false;
    if (!s_side) {
        cudaStreamCreateWithFlags(&s_side, cudaStreamNonBlocking);
        cudaEventCreateWithFlags(&ev_fork, cudaEventDisableTiming);
        cudaEventCreateWithFlags(&ev_join, cudaEventDisableTiming);
    }
    if (!attr_set) {
        cudaFuncSetAttribute(k_gemm_tc, cudaFuncAttributeMaxDynamicSharedMemorySize,
                             SMEM_GEMM);
        attr_set = true;
    }

    // count + scan on main stream (gemm epilogue needs dinv from scan)
    k_count_init<<<(n + 255) / 256, 256>>>(n);
    k_count<<<2048, 256>>>(ei, e);
    k_scan<<<1, 1024>>>(n);

    // fork: scatter + pool_init on side stream, GEMM1 on main
    cudaEventRecord(ev_fork, 0);
    cudaStreamWaitEvent(s_side, ev_fork, 0);
    k_scatter<<<2048, 256, 0, s_side>>>(ei, e);
    k_pool_init<<<(NG * FD + 255) / 256, 256, 0, s_side>>>();
    cudaEventRecord(ev_join, s_side);

    k_gemm_tc<<<gemm_blocks, 256, SMEM_GEMM>>>(x, w1, n, 0);
    cudaStreamWaitEvent(0, ev_join, 0);

    // layer 1
    k_aggregate<<<4096, 256>>>(b1, n);
    // layer 2 (aggregate fused with pooling)
    k_gemm_tc<<<gemm_blocks, 256, SMEM_GEMM>>>(x, w2, n, 1);
    k_agg_pool<<<2048, 256>>>(b2, batch, n);

    k_final<<<NG, 32>>>(wc, bc, out);
}